// round 14
// baseline (speedup 1.0000x reference)
#include <cuda_runtime.h>
#include <math.h>

#define BB   32
#define TT   400
#define MELD 80
#define LLd  256
#define UU   512
#define MMa  200
#define U4   2048
#define U3   1536
#define BT   (BB*TT)
#define NBLK 148
#define NTHR 1024
#define HN   (UU*BB)

__device__ __align__(16) float g_inT [BT*MELD];
__device__ __align__(16) float g_ph  [BT*UU];
__device__ __align__(16) float g_xp  [BT*LLd];
__device__ __align__(16) float g_keys[BB*MMa*UU];
__device__ __align__(16) float g_xpart[(size_t)BT*U4];
__device__ __align__(16) float g_x   [BT*UU];
__device__ __align__(16) float g_xsum[BT*UU];       // x + y1 (GRU1 out)
__device__ __align__(16) float g_xsum2[BT*UU];      // x + y1 + y2 (GRU2 out)
__device__ __align__(16) float g_xz  [(size_t)BT*U3];
__device__ __align__(16) float g_hT  [HN];
__device__ __align__(16) float g_q   [BB*UU];
__device__ __align__(16) float g_rec [U4*BB];
__device__ __align__(16) float g_actxT[2*LLd*BB];
__device__ __align__(16) float g_stats[BB*4];
__device__ __align__(16) float g_h1T[2*HN];
__device__ __align__(16) float g_h2T[2*HN];
__device__ int g_fq[32];
__device__ int g_frec[128];
__device__ int g_fctx[64];
__device__ int g_fh[64];
__device__ int g_f1[64];
__device__ int g_f2[64];
__device__ unsigned g_cnt = 0;
__device__ unsigned g_gen = 0;

__device__ __forceinline__ unsigned ld_acq_u(const unsigned* p) {
    unsigned v; asm volatile("ld.acquire.gpu.u32 %0, [%1];" : "=r"(v) : "l"(p)); return v;
}
// RELAXED poll load — independent, not ordered, cannot be hoisted
__device__ __forceinline__ int ld_relax(const int* p) {
    int v; asm volatile("ld.relaxed.gpu.global.b32 %0, [%1];" : "=r"(v) : "l"(p)); return v;
}
__device__ __forceinline__ void grid_barrier0(unsigned nb)
{
    __syncthreads();
    if (threadIdx.x == 0) {
        __threadfence();
        unsigned my   = ld_acq_u(&g_gen);
        unsigned prev = atomicAdd(&g_cnt, 1u);
        if (prev == nb - 1u) {
            atomicExch(&g_cnt, 0u);
            __threadfence();
            atomicAdd(&g_gen, 1u);
        } else {
            while (ld_acq_u(&g_gen) == my) { __nanosleep(32); }
        }
        __threadfence();
    }
    __syncthreads();
}
// relaxed-poll + single acquire fence after success
__device__ __forceinline__ void wait_flags(const int* flags, int count, int target)
{
    if (threadIdx.x < 32) {
        bool ok; int spins = 0;
        do {
            ok = true;
            for (int i = threadIdx.x; i < count; i += 32)
                ok &= (ld_relax(flags + i) >= target);
            if (!ok && ++spins > 256) __nanosleep(128);
        } while (!__all_sync(0xffffffffu, ok));
        asm volatile("fence.acq_rel.gpu;" ::: "memory");
    }
    __syncthreads();
}
__device__ __forceinline__ void arrive(int* flag, int v)
{
    __syncthreads();
    if (threadIdx.x == 0) {
        __threadfence();
        asm volatile("st.release.gpu.global.b32 [%0], %1;" :: "l"(flag), "r"(v) : "memory");
    }
}
__device__ __forceinline__ float sig(float x) { return 1.f / (1.f + __expf(-x)); }
__device__ __forceinline__ float tanh_ap(float x) {
    float y; asm("tanh.approx.f32 %0, %1;" : "=f"(y) : "f"(x)); return y;
}

__global__ void repack_inputs(const float* __restrict__ in)
{
    int i = blockIdx.x * blockDim.x + threadIdx.x;
    if (i < BT * MELD) {
        int d = i % MELD, r = i / MELD;
        int t = r >> 5, b = r & 31;
        g_inT[i] = in[((size_t)b * TT + t) * MELD + d];
    }
}

// ---------------- 128x128x16 fp32 GEMM ----------------
__global__ void __launch_bounds__(256) gemm128(
    const float* __restrict__ A, const float* __restrict__ W,
    const float* __restrict__ bias, float* __restrict__ C,
    int N, int K, int doRelu, int remapTB)
{
    __shared__ float Asf[16*132];
    __shared__ float Bsf[16*128];
    const int tid = threadIdx.x;
    const int m0 = blockIdx.y * 128, n0 = blockIdx.x * 128;
    const int tx = tid & 15, ty = tid >> 4;
    const int ar = tid >> 2, ak = (tid & 3) * 4;
    const int br = tid >> 5, bn = (tid & 31) * 4;
    float acc[8][8] = {};
    for (int k0 = 0; k0 < K; k0 += 16) {
#pragma unroll
        for (int h = 0; h < 2; h++) {
            int row = ar + 64*h;
            float4 a4 = *(const float4*)&A[(size_t)(m0 + row) * K + k0 + ak];
            Asf[(ak+0)*132 + row] = a4.x; Asf[(ak+1)*132 + row] = a4.y;
            Asf[(ak+2)*132 + row] = a4.z; Asf[(ak+3)*132 + row] = a4.w;
        }
#pragma unroll
        for (int h = 0; h < 2; h++) {
            int gn = n0 + bn;
            float4 b4 = make_float4(0.f,0.f,0.f,0.f);
            if (gn < N) b4 = *(const float4*)&W[(size_t)(k0 + br + 8*h) * N + gn];
            *(float4*)&Bsf[(br+8*h)*128 + bn] = b4;
        }
        __syncthreads();
#pragma unroll
        for (int kk = 0; kk < 16; kk++) {
            float a[8], bv[8];
            *(float4*)&a[0]  = *(const float4*)&Asf[kk*132 + ty*8];
            *(float4*)&a[4]  = *(const float4*)&Asf[kk*132 + ty*8 + 4];
            *(float4*)&bv[0] = *(const float4*)&Bsf[kk*128 + tx*8];
            *(float4*)&bv[4] = *(const float4*)&Bsf[kk*128 + tx*8 + 4];
#pragma unroll
            for (int i = 0; i < 8; i++)
#pragma unroll
                for (int j = 0; j < 8; j++) acc[i][j] += a[i] * bv[j];
        }
        __syncthreads();
    }
#pragma unroll
    for (int i = 0; i < 8; i++) {
        int row = m0 + ty*8 + i;
#pragma unroll
        for (int h = 0; h < 2; h++) {
            int col = n0 + tx*8 + h*4;
            if (col >= N) continue;
            float4 v;
            v.x = acc[i][h*4+0]; v.y = acc[i][h*4+1];
            v.z = acc[i][h*4+2]; v.w = acc[i][h*4+3];
            if (bias) {
                float4 bb = *(const float4*)&bias[col];
                v.x += bb.x; v.y += bb.y; v.z += bb.z; v.w += bb.w;
            }
            if (doRelu) {
                v.x = fmaxf(v.x, 0.f); v.y = fmaxf(v.y, 0.f);
                v.z = fmaxf(v.z, 0.f); v.w = fmaxf(v.w, 0.f);
            }
            size_t oi;
            if (remapTB) { int t = row >> 5, b = row & 31; oi = ((size_t)b * TT + t) * N + col; }
            else         { oi = (size_t)row * N + col; }
            *(float4*)&C[oi] = v;
        }
    }
}

// ============================================================
// persistent attention-LSTM (R7/R13-identical structure)
// ============================================================
#define SMF_L 20480
__global__ void __launch_bounds__(NTHR, 1) lstm_attn(
    const float* __restrict__ attended,
    const float* __restrict__ qW, const float* __restrict__ qb,
    const float* __restrict__ vW, const float* __restrict__ vb,
    const float* __restrict__ lstmK, const float* __restrict__ lstmR)
{
    extern __shared__ float sm[];
    const int tid = threadIdx.x, bid = blockIdx.x;
    const int lane = tid & 31, wid = tid >> 5;
    float* hT = sm;
    float* pA = sm + 16384;
    float* q_s  = sm;
    float* v_s  = sm + 512;
    float* sc   = sm + 1024;
    float* red  = sm + 1152;
    float* ctxp = sm + 1280;
    float* a1s  = sm;
    float* a2s  = sm + 32;
    float* ctxT = sm + 64;
    float* pC   = sm + 64 + 8192;
    float* zsm  = sm + 64 + 16384;

    const int unit1 = (bid < 84) ? bid : (bid < 116 ? 128 + (bid - 84) : bid - 32);
    const int unit2 = (bid >= 84 && bid < 96) ? 116 + (bid - 84) : -1;

    if (tid == 0) {
        if (bid < 32)  g_fq[bid] = 0;
        if (bid < 128) g_frec[bid] = 0;
        if (bid < 64)  { g_fctx[bid] = 0; g_fh[bid] = 0; }
    }
    for (int i = bid*NTHR + tid; i < HN; i += NBLK*NTHR) g_hT[i] = 0.f;
    float creg = 0.f;
    float vb0 = 0.f;
    if (bid < 64) vb0 = __ldg(vb);
    grid_barrier0(NBLK);

    const float4* R4  = (const float4*)lstmR;
    const float4* qW4 = (const float4*)qW;
    const float4* K24 = (const float4*)(lstmK + (size_t)LLd * U4);

    for (int t = 0; t < TT; ++t) {
        wait_flags(g_fh, 64, t);
        for (int i = tid; i < 4096; i += NTHR)
            ((float4*)hT)[i] = __ldcg((const float4*)g_hT + i);
        __syncthreads();

        for (int pass = 0; pass < 2; ++pass) {
            int u = (pass == 0) ? unit1 : unit2;
            if (u < 0) break;
            const int isq = (u >= 128);
            const int c0 = (isq ? (u - 128) : u) * 16;
            const float4* W4 = isq ? qW4 : R4;
            const int wstride = isq ? 128 : 512;
            {
                const int b = tid & 31, cq = (tid >> 5) & 3, ks = tid >> 7;
                const float4* wp = W4 + (size_t)(ks * 64) * wstride + (c0 >> 2) + cq;
                const float* hp = hT + (ks * 64) * 32 + b;
                float4 acc = make_float4(0.f,0.f,0.f,0.f);
#pragma unroll 8
                for (int k = 0; k < 64; ++k) {
                    float hv = hp[k * 32];
                    float4 w = __ldg(wp); wp += wstride;
                    acc.x += hv*w.x; acc.y += hv*w.y; acc.z += hv*w.z; acc.w += hv*w.w;
                }
                float* pd = pA + ks*512 + (cq*4)*32 + b;
                pd[0] = acc.x; pd[32] = acc.y; pd[64] = acc.z; pd[96] = acc.w;
            }
            __syncthreads();
            if (tid < 512) {
                const int c = tid >> 5, b = tid & 31;
                float s = 0.f;
#pragma unroll
                for (int j = 0; j < 8; ++j) s += pA[j*512 + c*32 + b];
                if (isq) {
                    s += __ldg(qb + c0 + c);
                    g_q[b*UU + c0 + c] = s;
                } else {
                    s += __ldcg(&g_xpart[((size_t)t*BB + b)*U4 + c0 + c]);
                    g_rec[(c0 + c)*32 + b] = s;
                }
            }
            arrive(isq ? &g_fq[u - 128] : &g_frec[u], t + 1);
        }

        if (bid < 64) {
            const int b = bid >> 1, half = bid & 1, m0h = half * 100;
            wait_flags(g_fq, 32, t + 1);
            if (tid < UU) { q_s[tid] = __ldcg(&g_q[b*UU + tid]); v_s[tid] = __ldg(vW + tid); }
            __syncthreads();
            for (int m = wid; m < 100; m += 32) {
                const float* krow = g_keys + ((size_t)(b*MMa + m0h + m)) * UU;
                float acc = 0.f;
#pragma unroll
                for (int jj = 0; jj < 16; ++jj) {
                    int uu = lane + 32*jj;
                    acc += v_s[uu] * tanh_ap(__ldg(krow + uu) + q_s[uu]);
                }
#pragma unroll
                for (int o = 16; o > 0; o >>= 1) acc += __shfl_down_sync(0xffffffffu, acc, o);
                if (lane == 0) sc[m] = acc + vb0;
            }
            __syncthreads();
            if (tid < 128) red[tid] = (tid < 100) ? sc[tid] : -1e30f;
            __syncthreads();
            for (int s = 64; s > 0; s >>= 1) { if (tid < s) red[tid] = fmaxf(red[tid], red[tid+s]); __syncthreads(); }
            float mx = red[0];
            __syncthreads();
            if (tid < 128) { float e = (tid < 100) ? __expf(sc[tid] - mx) : 0.f; sc[tid] = e; red[tid] = e; }
            __syncthreads();
            for (int s = 64; s > 0; s >>= 1) { if (tid < s) red[tid] += red[tid+s]; __syncthreads(); }
            float ssum = red[0];
            __syncthreads();
            {
                const int d = tid & 255, mp = tid >> 8;
                const float* att = attended + ((size_t)(b*MMa + m0h + mp*25)) * LLd + d;
                float acc = 0.f;
#pragma unroll
                for (int m = 0; m < 25; ++m) acc += sc[mp*25 + m] * __ldg(att + (size_t)m * LLd);
                ctxp[mp*256 + d] = acc;
            }
            __syncthreads();
            if (tid < 256)
                g_actxT[half*8192 + tid*32 + b] =
                    ctxp[tid] + ctxp[256+tid] + ctxp[512+tid] + ctxp[768+tid];
            if (tid == 0) { g_stats[b*4 + half*2] = mx; g_stats[b*4 + half*2 + 1] = ssum; }
            arrive(&g_fctx[bid], t + 1);

            const int u0 = bid * 8;
            wait_flags(g_fctx, 64, t + 1);
            wait_flags(g_frec, 128, t + 1);
            if (tid < 32) {
                float m1 = __ldcg(&g_stats[tid*4 + 0]), s1 = __ldcg(&g_stats[tid*4 + 1]);
                float m2 = __ldcg(&g_stats[tid*4 + 2]), s2 = __ldcg(&g_stats[tid*4 + 3]);
                float mxa = fmaxf(m1, m2);
                float w1 = __expf(m1 - mxa), w2 = __expf(m2 - mxa);
                float inv = 1.f / (w1*s1 + w2*s2);
                a1s[tid] = w1 * inv; a2s[tid] = w2 * inv;
            }
            __syncthreads();
            for (int i = tid; i < 8192; i += NTHR) {
                int b2 = i & 31;
                ctxT[i] = a1s[b2]*__ldcg(&g_actxT[i]) + a2s[b2]*__ldcg(&g_actxT[8192 + i]);
            }
            __syncthreads();
            {
                const int b2 = tid & 31, g = (tid >> 5) & 3, ks = tid >> 7;
                const float4* wp = K24 + (size_t)(ks*32)*512 + ((g*UU + u0) >> 2);
                const float* cp = ctxT + (ks*32)*32 + b2;
                float4 a0 = make_float4(0.f,0.f,0.f,0.f);
                float4 a1 = make_float4(0.f,0.f,0.f,0.f);
#pragma unroll 8
                for (int k = 0; k < 32; ++k) {
                    float cv = cp[k*32];
                    float4 w0 = __ldg(wp), w1 = __ldg(wp + 1); wp += 512;
                    a0.x += cv*w0.x; a0.y += cv*w0.y; a0.z += cv*w0.z; a0.w += cv*w0.w;
                    a1.x += cv*w1.x; a1.y += cv*w1.y; a1.z += cv*w1.z; a1.w += cv*w1.w;
                }
                float* pd = pC + ks*1024 + (g*8)*32 + b2;
                pd[0]   = a0.x; pd[32]  = a0.y; pd[64]  = a0.z; pd[96]  = a0.w;
                pd[128] = a1.x; pd[160] = a1.y; pd[192] = a1.z; pd[224] = a1.w;
            }
            __syncthreads();
            {
                const int g = tid >> 8, uu = (tid >> 5) & 7, b2 = tid & 31;
                float z = 0.f;
#pragma unroll
                for (int j = 0; j < 8; ++j) z += pC[j*1024 + (g*8 + uu)*32 + b2];
                z += __ldcg(&g_rec[(g*UU + u0 + uu)*32 + b2]);
                zsm[tid] = z;
            }
            __syncthreads();
            if (tid < 256) {
                const int uu = tid >> 5, b2 = tid & 31;
                float ig = sig(zsm[uu*32 + b2]);
                float fg = sig(zsm[256 + uu*32 + b2]);
                float gg = tanhf(zsm[512 + uu*32 + b2]);
                float og = sig(zsm[768 + uu*32 + b2]);
                float cn = fg * creg + ig * gg;
                creg = cn;
                float hn = og * tanhf(cn);
                g_hT[(u0 + uu)*32 + b2] = hn;
                g_x[((size_t)t*BB + b2)*UU + u0 + uu] = hn;
            }
            arrive(&g_fh[bid], t + 1);
        }
    }
}

// ---- 24-col (3 gates x 8 cells) batched matvec, k=512, + bias -> rr ----
__device__ __forceinline__ void mv24(
    const float4* W4, const float* vec, float* part, float* rr,
    const float* bias, int u0, int tid)
{
    if (tid < 768) {
        const int b = tid & 31, rest = tid >> 5;
        const int g = rest >> 3, ks = rest & 7;
        const float4* wp = W4 + (size_t)(ks*64)*384 + ((g*UU + u0) >> 2);
        const float* hp = vec + (ks*64)*32 + b;
        float4 a0 = make_float4(0.f,0.f,0.f,0.f);
        float4 a1 = make_float4(0.f,0.f,0.f,0.f);
#pragma unroll 8
        for (int k = 0; k < 64; ++k) {
            float hv = hp[k*32];
            float4 w0 = __ldg(wp), w1 = __ldg(wp + 1); wp += 384;
            a0.x += hv*w0.x; a0.y += hv*w0.y; a0.z += hv*w0.z; a0.w += hv*w0.w;
            a1.x += hv*w1.x; a1.y += hv*w1.y; a1.z += hv*w1.z; a1.w += hv*w1.w;
        }
        float* pd = part + ks*768 + (g*8)*32 + b;
        pd[0]   = a0.x; pd[32]  = a0.y; pd[64]  = a0.z; pd[96]  = a0.w;
        pd[128] = a1.x; pd[160] = a1.y; pd[192] = a1.z; pd[224] = a1.w;
    }
    __syncthreads();
    if (tid < 768) {
        const int c = tid >> 5, b = tid & 31, g = c >> 3;
        float s = 0.f;
#pragma unroll
        for (int j = 0; j < 8; ++j) s += part[j*768 + c*32 + b];
        rr[c*32 + b] = s + __ldg(bias + g*UU + u0 + (c & 7));
    }
    __syncthreads();
}

// ============================================================
// fused GRU1+GRU2, pipelined: blocks 0..63 GRU1(t=s), 64..127 GRU2(t=s-1)
// ============================================================
#define SMF_F 40448
__global__ void __launch_bounds__(NTHR, 1) fused_gru(
    const float* __restrict__ g1R, const float* __restrict__ g1b,
    const float* __restrict__ g2R, const float* __restrict__ g2K,
    const float* __restrict__ g2b)
{
    extern __shared__ float sm[];
    float* hS   = sm;
    float* xS   = sm + 16384;
    float* part = sm + 32768;
    float* rrh  = sm + 38912;
    float* rrx  = sm + 39680;
    const int tid = threadIdx.x, bid = blockIdx.x;
    const int isg2 = (bid >= 64);
    const int u0 = (isg2 ? bid - 64 : bid) * 8;

    if (tid == 0) { if (isg2) g_f2[bid-64] = 0; else g_f1[bid] = 0; }
    for (int i = bid*NTHR + tid; i < 2*HN; i += 128*NTHR) { g_h1T[i] = 0.f; g_h2T[i] = 0.f; }
    grid_barrier0(128);

    const float4* R14 = (const float4*)g1R;
    const float4* R24 = (const float4*)g2R;
    const float4* K24 = (const float4*)g2K;

    for (int s = 0; s <= TT; ++s) {
        if (!isg2) {
            if (s < TT) {
                const int t = s;
                wait_flags(g_f1, 64, t);
                {
                    const float4* hb = (const float4*)(g_h1T + ((t+1)&1)*HN);
                    for (int i = tid; i < 4096; i += NTHR) ((float4*)hS)[i] = __ldcg(hb + i);
                }
                __syncthreads();
                mv24(R14, hS, part, rrh, g1b + U3, u0, tid);
                if (tid < 256) {
                    const int cell = tid >> 5, b = tid & 31;
                    const int ug = u0 + cell;
                    const float* xzr = g_xz + ((size_t)t*BB + b) * U3;
                    float z = sig(__ldg(xzr + ug)           + rrh[cell*32 + b]);
                    float r = sig(__ldg(xzr + UU + ug)      + rrh[(8+cell)*32 + b]);
                    float hh = tanhf(__ldg(xzr + 2*UU + ug) + r * rrh[(16+cell)*32 + b]);
                    float hn = z * hS[ug*32 + b] + (1.f - z) * hh;
                    g_h1T[(t&1)*HN + ug*32 + b] = hn;
                    size_t oi = ((size_t)t*BB + b)*UU + ug;
                    g_xsum[oi] = __ldcg(&g_x[oi]) + hn;
                }
                arrive(&g_f1[bid], t + 1);
            }
        } else {
            if (s >= 1) {
                const int t = s - 1;
                wait_flags(g_f1, 64, t + 1);
                wait_flags(g_f2, 64, t);
                {
                    const float4* hb = (const float4*)(g_h2T + ((t+1)&1)*HN);
                    const float4* xb = (const float4*)(g_xsum + (size_t)t*HN);
                    for (int i = tid; i < 4096; i += NTHR) {
                        ((float4*)hS)[i] = __ldcg(hb + i);
                        float4 v = __ldcg(xb + i);
                        int b = i >> 7, u = (i & 127) * 4;
                        xS[(u+0)*32 + b] = v.x; xS[(u+1)*32 + b] = v.y;
                        xS[(u+2)*32 + b] = v.z; xS[(u+3)*32 + b] = v.w;
                    }
                }
                __syncthreads();
                mv24(R24, hS, part, rrh, g2b + U3, u0, tid);
                mv24(K24, xS, part, rrx, g2b,      u0, tid);
                if (tid < 256) {
                    const int cell = tid >> 5, b = tid & 31;
                    const int ug = u0 + cell;
                    float z = sig(rrx[cell*32 + b]        + rrh[cell*32 + b]);
                    float r = sig(rrx[(8+cell)*32 + b]    + rrh[(8+cell)*32 + b]);
                    float hh = tanhf(rrx[(16+cell)*32 + b] + r * rrh[(16+cell)*32 + b]);
                    float hn = z * hS[ug*32 + b] + (1.f - z) * hh;
                    g_h2T[(t&1)*HN + ug*32 + b] = hn;
                    g_xsum2[((size_t)t*BB + b)*UU + ug] = xS[ug*32 + b] + hn;
                }
                arrive(&g_f2[bid - 64], t + 1);
            }
        }
    }
}

// ---------------- launch ----------------
extern "C" void kernel_launch(void* const* d_in, const int* in_sizes, int n_in,
                              void* d_out, int out_size)
{
    const float* inputs   = (const float*)d_in[0];
    const float* attended = (const float*)d_in[1];
    const float* pre_W1   = (const float*)d_in[2];
    const float* pre_b1   = (const float*)d_in[3];
    const float* pre_W2   = (const float*)d_in[4];
    const float* pre_b2   = (const float*)d_in[5];
    const float* key_W    = (const float*)d_in[6];
    const float* key_b    = (const float*)d_in[7];
    const float* query_W  = (const float*)d_in[8];
    const float* query_b  = (const float*)d_in[9];
    const float* attnv_W  = (const float*)d_in[10];
    const float* attnv_b  = (const float*)d_in[11];
    const float* lstm_K   = (const float*)d_in[12];
    const float* lstm_R   = (const float*)d_in[13];
    const float* lstm_b   = (const float*)d_in[14];
    const float* gru1_K   = (const float*)d_in[15];
    const float* gru1_R   = (const float*)d_in[16];
    const float* gru1_b   = (const float*)d_in[17];
    const float* gru2_K   = (const float*)d_in[18];
    const float* gru2_R   = (const float*)d_in[19];
    const float* gru2_b   = (const float*)d_in[20];
    const float* proj_W   = (const float*)d_in[21];
    float* out = (float*)d_out;

    float *inT, *ph, *xp, *keys, *xpart, *x, *xz, *xsum2;
    cudaGetSymbolAddress((void**)&inT,   g_inT);
    cudaGetSymbolAddress((void**)&ph,    g_ph);
    cudaGetSymbolAddress((void**)&xp,    g_xp);
    cudaGetSymbolAddress((void**)&keys,  g_keys);
    cudaGetSymbolAddress((void**)&xpart, g_xpart);
    cudaGetSymbolAddress((void**)&x,     g_x);
    cudaGetSymbolAddress((void**)&xz,    g_xz);
    cudaGetSymbolAddress((void**)&xsum2, g_xsum2);

    cudaFuncSetAttribute(lstm_attn, cudaFuncAttributeMaxDynamicSharedMemorySize,
                         SMF_L * (int)sizeof(float));
    cudaFuncSetAttribute(fused_gru, cudaFuncAttributeMaxDynamicSharedMemorySize,
                         SMF_F * (int)sizeof(float));

    repack_inputs<<<(BT*MELD + 255)/256, 256>>>(inputs);
    gemm128<<<dim3(4, 100), 256>>>(inT, pre_W1, pre_b1, ph, UU,  MELD, 1, 0);
    gemm128<<<dim3(2, 100), 256>>>(ph,  pre_W2, pre_b2, xp, LLd, UU,   1, 0);
    gemm128<<<dim3(4, 50),  256>>>(attended, key_W, key_b, keys, UU, LLd, 0, 0);
    gemm128<<<dim3(16, 100), 256>>>(xp, lstm_K, lstm_b, xpart, U4, LLd, 0, 0);
    lstm_attn<<<NBLK, NTHR, SMF_L*sizeof(float)>>>(
        attended, query_W, query_b, attnv_W, attnv_b, lstm_K, lstm_R);
    gemm128<<<dim3(12, 100), 256>>>(x, gru1_K, gru1_b, xz, U3, UU, 0, 0);
    fused_gru<<<128, NTHR, SMF_F*sizeof(float)>>>(gru1_R, gru1_b, gru2_R, gru2_K, gru2_b);
    gemm128<<<dim3(1, 100), 256>>>(xsum2, proj_W, nullptr, out, MELD, UU, 1, 1);
}

// round 15
// speedup vs baseline: 1.2667x; 1.2667x over previous
#include <cuda_runtime.h>
#include <math.h>

#define BB   32
#define TT   400
#define MELD 80
#define LLd  256
#define UU   512
#define MMa  200
#define U4   2048
#define U3   1536
#define BT   (BB*TT)
#define NTHR 1024
#define HN   (UU*BB)

__device__ __align__(16) float g_inT [BT*MELD];
__device__ __align__(16) float g_ph  [BT*UU];
__device__ __align__(16) float g_xp  [BT*LLd];
__device__ __align__(16) float g_keys[BB*MMa*UU];
__device__ __align__(16) float g_xpart[(size_t)BT*U4];
__device__ __align__(16) float g_x   [BT*UU];
__device__ __align__(16) float g_xsum[BT*UU];
__device__ __align__(16) float g_xsum2[BT*UU];
__device__ __align__(16) float g_hT  [HN];
__device__ __align__(16) float g_q   [BB*UU];
__device__ __align__(16) float g_rec [U4*BB];
__device__ __align__(16) float g_actxT[2*LLd*BB];
__device__ __align__(16) float g_stats[BB*4];
__device__ __align__(16) float g_h1T[2*HN];
__device__ __align__(16) float g_h2T[2*HN];
__device__ int g_fq[64];
__device__ int g_frec[64];
__device__ int g_fctx[64];
__device__ int g_fh[64];
__device__ int g_f1[32];
__device__ int g_f2[32];
__device__ unsigned g_cnt = 0;
__device__ unsigned g_gen = 0;

__device__ __forceinline__ unsigned ld_acq_u(const unsigned* p) {
    unsigned v; asm volatile("ld.acquire.gpu.u32 %0, [%1];" : "=r"(v) : "l"(p)); return v;
}
__device__ __forceinline__ int ld_relax(const int* p) {
    int v; asm volatile("ld.relaxed.gpu.global.b32 %0, [%1];" : "=r"(v) : "l"(p)); return v;
}
__device__ __forceinline__ void grid_barrier0(unsigned nb)
{
    __syncthreads();
    if (threadIdx.x == 0) {
        __threadfence();
        unsigned my   = ld_acq_u(&g_gen);
        unsigned prev = atomicAdd(&g_cnt, 1u);
        if (prev == nb - 1u) {
            atomicExch(&g_cnt, 0u);
            __threadfence();
            atomicAdd(&g_gen, 1u);
        } else {
            while (ld_acq_u(&g_gen) == my) { __nanosleep(32); }
        }
        __threadfence();
    }
    __syncthreads();
}
__device__ __forceinline__ void wait_flags(const int* flags, int count, int target)
{
    if (threadIdx.x < 32) {
        bool ok; int spins = 0;
        do {
            ok = true;
            for (int i = threadIdx.x; i < count; i += 32)
                ok &= (ld_relax(flags + i) >= target);
            if (!ok && ++spins > 512) __nanosleep(128);
        } while (!__all_sync(0xffffffffu, ok));
        asm volatile("fence.acq_rel.gpu;" ::: "memory");
    }
    __syncthreads();
}
__device__ __forceinline__ void arrive(int* flag, int v)
{
    __syncthreads();
    if (threadIdx.x == 0) {
        __threadfence();
        asm volatile("st.release.gpu.global.b32 [%0], %1;" :: "l"(flag), "r"(v) : "memory");
    }
}
__device__ __forceinline__ float sig(float x) { return 1.f / (1.f + __expf(-x)); }
__device__ __forceinline__ float tanh_ap(float x) {
    float y; asm("tanh.approx.f32 %0, %1;" : "=f"(y) : "f"(x)); return y;
}

__global__ void repack_inputs(const float* __restrict__ in)
{
    int i = blockIdx.x * blockDim.x + threadIdx.x;
    if (i < BT * MELD) {
        int d = i % MELD, r = i / MELD;
        int t = r >> 5, b = r & 31;
        g_inT[i] = in[((size_t)b * TT + t) * MELD + d];
    }
}

// ---------------- 128x128x16 fp32 GEMM ----------------
__global__ void __launch_bounds__(256) gemm128(
    const float* __restrict__ A, const float* __restrict__ W,
    const float* __restrict__ bias, float* __restrict__ C,
    int N, int K, int doRelu, int remapTB)
{
    __shared__ float Asf[16*132];
    __shared__ float Bsf[16*128];
    const int tid = threadIdx.x;
    const int m0 = blockIdx.y * 128, n0 = blockIdx.x * 128;
    const int tx = tid & 15, ty = tid >> 4;
    const int ar = tid >> 2, ak = (tid & 3) * 4;
    const int br = tid >> 5, bn = (tid & 31) * 4;
    float acc[8][8] = {};
    for (int k0 = 0; k0 < K; k0 += 16) {
#pragma unroll
        for (int h = 0; h < 2; h++) {
            int row = ar + 64*h;
            float4 a4 = *(const float4*)&A[(size_t)(m0 + row) * K + k0 + ak];
            Asf[(ak+0)*132 + row] = a4.x; Asf[(ak+1)*132 + row] = a4.y;
            Asf[(ak+2)*132 + row] = a4.z; Asf[(ak+3)*132 + row] = a4.w;
        }
#pragma unroll
        for (int h = 0; h < 2; h++) {
            int gn = n0 + bn;
            float4 b4 = make_float4(0.f,0.f,0.f,0.f);
            if (gn < N) b4 = *(const float4*)&W[(size_t)(k0 + br + 8*h) * N + gn];
            *(float4*)&Bsf[(br+8*h)*128 + bn] = b4;
        }
        __syncthreads();
#pragma unroll
        for (int kk = 0; kk < 16; kk++) {
            float a[8], bv[8];
            *(float4*)&a[0]  = *(const float4*)&Asf[kk*132 + ty*8];
            *(float4*)&a[4]  = *(const float4*)&Asf[kk*132 + ty*8 + 4];
            *(float4*)&bv[0] = *(const float4*)&Bsf[kk*128 + tx*8];
            *(float4*)&bv[4] = *(const float4*)&Bsf[kk*128 + tx*8 + 4];
#pragma unroll
            for (int i = 0; i < 8; i++)
#pragma unroll
                for (int j = 0; j < 8; j++) acc[i][j] += a[i] * bv[j];
        }
        __syncthreads();
    }
#pragma unroll
    for (int i = 0; i < 8; i++) {
        int row = m0 + ty*8 + i;
#pragma unroll
        for (int h = 0; h < 2; h++) {
            int col = n0 + tx*8 + h*4;
            if (col >= N) continue;
            float4 v;
            v.x = acc[i][h*4+0]; v.y = acc[i][h*4+1];
            v.z = acc[i][h*4+2]; v.w = acc[i][h*4+3];
            if (bias) {
                float4 bb = *(const float4*)&bias[col];
                v.x += bb.x; v.y += bb.y; v.z += bb.z; v.w += bb.w;
            }
            if (doRelu) {
                v.x = fmaxf(v.x, 0.f); v.y = fmaxf(v.y, 0.f);
                v.z = fmaxf(v.z, 0.f); v.w = fmaxf(v.w, 0.f);
            }
            size_t oi;
            if (remapTB) { int t = row >> 5, b = row & 31; oi = ((size_t)b * TT + t) * N + col; }
            else         { oi = (size_t)row * N + col; }
            *(float4*)&C[oi] = v;
        }
    }
}

// ---- 24-col (3 gates x 8 cells) batched matvec, k=512, + bias -> rr ----
__device__ __forceinline__ void mv24(
    const float4* W4, const float* vec, float* part, float* rr,
    const float* bias, int u0, int tid)
{
    if (tid < 768) {
        const int b = tid & 31, rest = tid >> 5;
        const int g = rest >> 3, ks = rest & 7;
        const float4* wp = W4 + (size_t)(ks*64)*384 + ((g*UU + u0) >> 2);
        const float* hp = vec + (ks*64)*32 + b;
        float4 a0 = make_float4(0.f,0.f,0.f,0.f);
        float4 a1 = make_float4(0.f,0.f,0.f,0.f);
#pragma unroll 8
        for (int k = 0; k < 64; ++k) {
            float hv = hp[k*32];
            float4 w0 = __ldg(wp), w1 = __ldg(wp + 1); wp += 384;
            a0.x += hv*w0.x; a0.y += hv*w0.y; a0.z += hv*w0.z; a0.w += hv*w0.w;
            a1.x += hv*w1.x; a1.y += hv*w1.y; a1.z += hv*w1.z; a1.w += hv*w1.w;
        }
        float* pd = part + ks*768 + (g*8)*32 + b;
        pd[0]   = a0.x; pd[32]  = a0.y; pd[64]  = a0.z; pd[96]  = a0.w;
        pd[128] = a1.x; pd[160] = a1.y; pd[192] = a1.z; pd[224] = a1.w;
    }
    __syncthreads();
    if (tid < 768) {
        const int c = tid >> 5, b = tid & 31, g = c >> 3;
        float s = 0.f;
#pragma unroll
        for (int j = 0; j < 8; ++j) s += part[j*768 + c*32 + b];
        rr[c*32 + b] = s + __ldg(bias + g*UU + u0 + (c & 7));
    }
    __syncthreads();
}

// ============================================================
// FUSED: blocks 0..63 LSTM(s) | 64..95 GRU1(s-2) | 96..127 GRU2(s-4)
// ============================================================
#define SMF_L 20480
#define SMF_F 41984
#define SMF_MAX SMF_F
__global__ void __launch_bounds__(NTHR, 1) fused_all(
    const float* __restrict__ attended,
    const float* __restrict__ qW, const float* __restrict__ qb,
    const float* __restrict__ vW, const float* __restrict__ vb,
    const float* __restrict__ lstmK, const float* __restrict__ lstmR,
    const float* __restrict__ g1R, const float* __restrict__ g1K, const float* __restrict__ g1b,
    const float* __restrict__ g2R, const float* __restrict__ g2K, const float* __restrict__ g2b)
{
    extern __shared__ float sm[];
    const int tid = threadIdx.x, bid = blockIdx.x;
    const int lane = tid & 31, wid = tid >> 5;

    if (tid == 0) {
        if (bid < 64) { g_fq[bid] = 0; g_frec[bid] = 0; g_fctx[bid] = 0; g_fh[bid] = 0; }
        else if (bid < 96) g_f1[bid-64] = 0;
        else g_f2[bid-96] = 0;
    }
    for (int i = bid*NTHR + tid; i < HN; i += 128*NTHR) g_hT[i] = 0.f;
    for (int i = bid*NTHR + tid; i < 2*HN; i += 128*NTHR) { g_h1T[i] = 0.f; g_h2T[i] = 0.f; }
    grid_barrier0(128);

    if (bid < 64) {
        // =================== LSTM ===================
        float* hT   = sm;            // 16384 (kept through rec)
        float* pA   = sm + 16384;    // 4096 (q/rec partials)
        float* q_s  = sm + 16384;    // B aliases (pA dead)
        float* v_s  = sm + 16896;
        float* sc   = sm + 17408;
        float* red  = sm + 17536;
        float* ctxp = sm + 17664;    // 1024
        float* ctxT = sm;            // C aliases (hT dead)
        float* pC   = sm + 8192;
        float* zsm  = sm + 16448;
        float* a1s  = sm + 17472;
        float* a2s  = sm + 17504;
        const int b = bid >> 1, half = bid & 1, m0h = half * 100;
        const int qc0 = bid * 8, rc0 = bid * 32, u0 = bid * 8;
        const float4* R4  = (const float4*)lstmR;
        const float4* qW4 = (const float4*)qW;
        const float4* K24 = (const float4*)(lstmK + (size_t)LLd * U4);
        float creg = 0.f;
        const float vb0 = __ldg(vb);

        for (int t = 0; t < TT; ++t) {
            wait_flags(g_fh, 64, t);
            for (int i = tid; i < 4096; i += NTHR)
                ((float4*)hT)[i] = __ldcg((const float4*)g_hT + i);
            __syncthreads();
            // ---- q slice: 8 cols ----
            {
                const int bb = tid & 31, cq = (tid >> 5) & 1, ks = tid >> 6;
                const float4* wp = qW4 + (size_t)(ks*32)*128 + (qc0 >> 2) + cq;
                const float* hp = hT + (ks*32)*32 + bb;
                float4 a = make_float4(0.f,0.f,0.f,0.f);
#pragma unroll 8
                for (int k = 0; k < 32; ++k) {
                    float hv = hp[k*32];
                    float4 w = __ldg(wp); wp += 128;
                    a.x += hv*w.x; a.y += hv*w.y; a.z += hv*w.z; a.w += hv*w.w;
                }
                float* pd = pA + ks*256 + (cq*4)*32 + bb;
                pd[0] = a.x; pd[32] = a.y; pd[64] = a.z; pd[96] = a.w;
            }
            __syncthreads();
            if (tid < 256) {
                const int c = tid >> 5, bb = tid & 31;
                float s = __ldg(qb + qc0 + c);
#pragma unroll
                for (int j = 0; j < 16; ++j) s += pA[j*256 + c*32 + bb];
                g_q[bb*UU + qc0 + c] = s;
            }
            arrive(&g_fq[bid], t + 1);
            // ---- B: attention for (b,half) ----
            wait_flags(g_fq, 64, t + 1);
            if (tid < UU) { q_s[tid] = __ldcg(&g_q[b*UU + tid]); v_s[tid] = __ldg(vW + tid); }
            __syncthreads();
            for (int m = wid; m < 100; m += 32) {
                const float* krow = g_keys + ((size_t)(b*MMa + m0h + m)) * UU;
                float acc = 0.f;
#pragma unroll
                for (int jj = 0; jj < 16; ++jj) {
                    int uu = lane + 32*jj;
                    acc += v_s[uu] * tanh_ap(__ldg(krow + uu) + q_s[uu]);
                }
#pragma unroll
                for (int o = 16; o > 0; o >>= 1) acc += __shfl_down_sync(0xffffffffu, acc, o);
                if (lane == 0) sc[m] = acc + vb0;
            }
            __syncthreads();
            if (tid < 128) red[tid] = (tid < 100) ? sc[tid] : -1e30f;
            __syncthreads();
            for (int st = 64; st > 0; st >>= 1) { if (tid < st) red[tid] = fmaxf(red[tid], red[tid+st]); __syncthreads(); }
            float mx = red[0];
            __syncthreads();
            if (tid < 128) { float e = (tid < 100) ? __expf(sc[tid] - mx) : 0.f; sc[tid] = e; red[tid] = e; }
            __syncthreads();
            for (int st = 64; st > 0; st >>= 1) { if (tid < st) red[tid] += red[tid+st]; __syncthreads(); }
            float ssum = red[0];
            __syncthreads();
            {
                const int d = tid & 255, mp = tid >> 8;
                const float* att = attended + ((size_t)(b*MMa + m0h + mp*25)) * LLd + d;
                float acc = 0.f;
#pragma unroll
                for (int m = 0; m < 25; ++m) acc += sc[mp*25 + m] * __ldg(att + (size_t)m * LLd);
                ctxp[mp*256 + d] = acc;
            }
            __syncthreads();
            if (tid < 256)
                g_actxT[half*8192 + tid*32 + b] =
                    ctxp[tid] + ctxp[256+tid] + ctxp[512+tid] + ctxp[768+tid];
            if (tid == 0) { g_stats[b*4 + half*2] = mx; g_stats[b*4 + half*2 + 1] = ssum; }
            arrive(&g_fctx[bid], t + 1);
            // ---- rec slice: 32 cols ----
            {
                const int bb = tid & 31, cq = (tid >> 5) & 7, ks = tid >> 8;
                const float4* wp = R4 + (size_t)(ks*128)*512 + (rc0 >> 2) + cq;
                const float* hp = hT + (ks*128)*32 + bb;
                float4 a = make_float4(0.f,0.f,0.f,0.f);
#pragma unroll 8
                for (int k = 0; k < 128; ++k) {
                    float hv = hp[k*32];
                    float4 w = __ldg(wp); wp += 512;
                    a.x += hv*w.x; a.y += hv*w.y; a.z += hv*w.z; a.w += hv*w.w;
                }
                float* pd = pA + ks*1024 + (cq*4)*32 + bb;
                pd[0] = a.x; pd[32] = a.y; pd[64] = a.z; pd[96] = a.w;
            }
            __syncthreads();
            {
                const int c = tid >> 5, bb = tid & 31;
                float s = __ldcg(&g_xpart[((size_t)t*BB + bb)*U4 + rc0 + c]);
#pragma unroll
                for (int j = 0; j < 4; ++j) s += pA[j*1024 + c*32 + bb];
                g_rec[(rc0 + c)*32 + bb] = s;
            }
            arrive(&g_frec[bid], t + 1);
            // ---- C: gates, cells u0..u0+8 for all b ----
            wait_flags(g_fctx, 64, t + 1);
            wait_flags(g_frec, 64, t + 1);
            if (tid < 32) {
                float m1 = __ldcg(&g_stats[tid*4 + 0]), s1 = __ldcg(&g_stats[tid*4 + 1]);
                float m2 = __ldcg(&g_stats[tid*4 + 2]), s2 = __ldcg(&g_stats[tid*4 + 3]);
                float mxa = fmaxf(m1, m2);
                float w1 = __expf(m1 - mxa), w2 = __expf(m2 - mxa);
                float inv = 1.f / (w1*s1 + w2*s2);
                a1s[tid] = w1 * inv; a2s[tid] = w2 * inv;
            }
            __syncthreads();
            for (int i = tid; i < 8192; i += NTHR) {
                int b2 = i & 31;
                ctxT[i] = a1s[b2]*__ldcg(&g_actxT[i]) + a2s[b2]*__ldcg(&g_actxT[8192 + i]);
            }
            __syncthreads();
            {
                const int b2 = tid & 31, g = (tid >> 5) & 3, ks = tid >> 7;
                const float4* wp = K24 + (size_t)(ks*32)*512 + ((g*UU + u0) >> 2);
                const float* cp = ctxT + (ks*32)*32 + b2;
                float4 a0 = make_float4(0.f,0.f,0.f,0.f);
                float4 a1 = make_float4(0.f,0.f,0.f,0.f);
#pragma unroll 8
                for (int k = 0; k < 32; ++k) {
                    float cv = cp[k*32];
                    float4 w0 = __ldg(wp), w1 = __ldg(wp + 1); wp += 512;
                    a0.x += cv*w0.x; a0.y += cv*w0.y; a0.z += cv*w0.z; a0.w += cv*w0.w;
                    a1.x += cv*w1.x; a1.y += cv*w1.y; a1.z += cv*w1.z; a1.w += cv*w1.w;
                }
                float* pd = pC + ks*1024 + (g*8)*32 + b2;
                pd[0]   = a0.x; pd[32]  = a0.y; pd[64]  = a0.z; pd[96]  = a0.w;
                pd[128] = a1.x; pd[160] = a1.y; pd[192] = a1.z; pd[224] = a1.w;
            }
            __syncthreads();
            {
                const int g = tid >> 8, uu = (tid >> 5) & 7, b2 = tid & 31;
                float z = 0.f;
#pragma unroll
                for (int j = 0; j < 8; ++j) z += pC[j*1024 + (g*8 + uu)*32 + b2];
                z += __ldcg(&g_rec[(g*UU + u0 + uu)*32 + b2]);
                zsm[tid] = z;
            }
            __syncthreads();
            if (tid < 256) {
                const int uu = tid >> 5, b2 = tid & 31;
                float ig = sig(zsm[uu*32 + b2]);
                float fg = sig(zsm[256 + uu*32 + b2]);
                float gg = tanhf(zsm[512 + uu*32 + b2]);
                float og = sig(zsm[768 + uu*32 + b2]);
                float cn = fg * creg + ig * gg;
                creg = cn;
                float hn = og * tanhf(cn);
                g_hT[(u0 + uu)*32 + b2] = hn;
                g_x[((size_t)t*BB + b2)*UU + u0 + uu] = hn;
            }
            arrive(&g_fh[bid], t + 1);
        }
    } else {
        // =================== GRU (both layers, pipelined) ===================
        float* hS   = sm;            // 16384
        float* xS   = sm + 16384;    // 16384
        float* part = sm + 32768;    // 6144
        float* rr0  = sm + 38912;    // 768 h-part cells 0-7
        float* rr1  = sm + 39680;    // 768 h-part cells 8-15
        float* rx0  = sm + 40448;    // 768 x-part
        float* rx1  = sm + 41216;    // 768
        const int isg2 = (bid >= 96);
        const int u0g = (isg2 ? bid - 96 : bid - 64) * 16;
        const int lag = isg2 ? 4 : 2;
        const float4* Rm = (const float4*)(isg2 ? g2R : g1R);
        const float4* Km = (const float4*)(isg2 ? g2K : g1K);
        const float* bi = isg2 ? g2b : g1b;
        const float* xin = isg2 ? g_xsum : g_x;
        float* hbuf = isg2 ? g_h2T : g_h1T;
        float* fout = isg2 ? g_xsum2 : g_xsum;
        int* fme  = isg2 ? g_f2 : g_f1;
        const int fidx = isg2 ? bid - 96 : bid - 64;

        for (int s = lag; s < TT + lag; ++s) {
            const int t = s - lag;
            // input ready: GRU1 needs fh>=t+1 ; GRU2 needs f1>=t+1
            if (isg2) wait_flags(g_f1, 32, t + 1);
            else      wait_flags(g_fh, 64, t + 1);
            wait_flags(fme, 32, t);
            {
                const float4* hb = (const float4*)(hbuf + ((t+1)&1)*HN);
                const float4* xb = (const float4*)(xin + (size_t)t*HN);
                for (int i = tid; i < 4096; i += NTHR) {
                    ((float4*)hS)[i] = __ldcg(hb + i);
                    float4 v = __ldcg(xb + i);
                    int bb = i >> 7, u = (i & 127) * 4;
                    xS[(u+0)*32 + bb] = v.x; xS[(u+1)*32 + bb] = v.y;
                    xS[(u+2)*32 + bb] = v.z; xS[(u+3)*32 + bb] = v.w;
                }
            }
            __syncthreads();
            mv24(Rm, hS, part, rr0, bi + U3, u0g,     tid);
            mv24(Rm, hS, part, rr1, bi + U3, u0g + 8, tid);
            mv24(Km, xS, part, rx0, bi,      u0g,     tid);
            mv24(Km, xS, part, rx1, bi,      u0g + 8, tid);
            if (tid < 512) {
                const int cell = tid >> 5, bb = tid & 31;
                const int ug = u0g + cell;
                float* rh = (cell < 8) ? rr0 : rr1;
                float* rx = (cell < 8) ? rx0 : rx1;
                const int cc = cell & 7;
                float z = sig(rx[cc*32 + bb]        + rh[cc*32 + bb]);
                float r = sig(rx[(8+cc)*32 + bb]    + rh[(8+cc)*32 + bb]);
                float hh = tanhf(rx[(16+cc)*32 + bb] + r * rh[(16+cc)*32 + bb]);
                float hn = z * hS[ug*32 + bb] + (1.f - z) * hh;
                hbuf[(t&1)*HN + ug*32 + bb] = hn;
                fout[((size_t)t*BB + bb)*UU + ug] = xS[ug*32 + bb] + hn;
            }
            arrive(&fme[fidx], t + 1);
        }
    }
}

// ---------------- launch ----------------
extern "C" void kernel_launch(void* const* d_in, const int* in_sizes, int n_in,
                              void* d_out, int out_size)
{
    const float* inputs   = (const float*)d_in[0];
    const float* attended = (const float*)d_in[1];
    const float* pre_W1   = (const float*)d_in[2];
    const float* pre_b1   = (const float*)d_in[3];
    const float* pre_W2   = (const float*)d_in[4];
    const float* pre_b2   = (const float*)d_in[5];
    const float* key_W    = (const float*)d_in[6];
    const float* key_b    = (const float*)d_in[7];
    const float* query_W  = (const float*)d_in[8];
    const float* query_b  = (const float*)d_in[9];
    const float* attnv_W  = (const float*)d_in[10];
    const float* attnv_b  = (const float*)d_in[11];
    const float* lstm_K   = (const float*)d_in[12];
    const float* lstm_R   = (const float*)d_in[13];
    const float* lstm_b   = (const float*)d_in[14];
    const float* gru1_K   = (const float*)d_in[15];
    const float* gru1_R   = (const float*)d_in[16];
    const float* gru1_b   = (const float*)d_in[17];
    const float* gru2_K   = (const float*)d_in[18];
    const float* gru2_R   = (const float*)d_in[19];
    const float* gru2_b   = (const float*)d_in[20];
    const float* proj_W   = (const float*)d_in[21];
    float* out = (float*)d_out;

    float *inT, *ph, *xp, *keys, *xpart, *xsum2;
    cudaGetSymbolAddress((void**)&inT,   g_inT);
    cudaGetSymbolAddress((void**)&ph,    g_ph);
    cudaGetSymbolAddress((void**)&xp,    g_xp);
    cudaGetSymbolAddress((void**)&keys,  g_keys);
    cudaGetSymbolAddress((void**)&xpart, g_xpart);
    cudaGetSymbolAddress((void**)&xsum2, g_xsum2);

    cudaFuncSetAttribute(fused_all, cudaFuncAttributeMaxDynamicSharedMemorySize,
                         SMF_MAX * (int)sizeof(float));

    repack_inputs<<<(BT*MELD + 255)/256, 256>>>(inputs);
    gemm128<<<dim3(4, 100), 256>>>(inT, pre_W1, pre_b1, ph, UU,  MELD, 1, 0);
    gemm128<<<dim3(2, 100), 256>>>(ph,  pre_W2, pre_b2, xp, LLd, UU,   1, 0);
    gemm128<<<dim3(4, 50),  256>>>(attended, key_W, key_b, keys, UU, LLd, 0, 0);
    gemm128<<<dim3(16, 100), 256>>>(xp, lstm_K, lstm_b, xpart, U4, LLd, 0, 0);
    fused_all<<<128, NTHR, SMF_MAX*sizeof(float)>>>(
        attended, query_W, query_b, attnv_W, attnv_b, lstm_K, lstm_R,
        gru1_R, gru1_K, gru1_b, gru2_R, gru2_K, gru2_b);
    gemm128<<<dim3(1, 100), 256>>>(xsum2, proj_W, nullptr, out, MELD, UU, 1, 1);
}